// round 2
// baseline (speedup 1.0000x reference)
#include <cuda_runtime.h>
#include <cstdint>

#define SEQ   512
#define BATCH 64
#define H     1024
#define H3    3072

// ---------------- device scratch (no cudaMalloc allowed) ----------------
__device__ float g_gi[(size_t)SEQ * BATCH * H3];  // raw encoded @ W_ih (bias added later)
__device__ float g_h[2][BATCH * H];               // h ping-pong

// ---------------- helpers ----------------
__device__ __forceinline__ unsigned f2tf(float x) {
    unsigned r;
    asm("cvt.rna.tf32.f32 %0, %1;" : "=r"(r) : "f"(x));
    return r;
}

__device__ __forceinline__ void mma8(float c[4], const unsigned a[4],
                                     unsigned b0, unsigned b1) {
    asm volatile(
        "mma.sync.aligned.m16n8k8.row.col.f32.tf32.tf32.f32 "
        "{%0,%1,%2,%3},{%4,%5,%6,%7},{%8,%9},{%0,%1,%2,%3};"
        : "+f"(c[0]), "+f"(c[1]), "+f"(c[2]), "+f"(c[3])
        : "r"(a[0]), "r"(a[1]), "r"(a[2]), "r"(a[3]), "r"(b0), "r"(b1));
}

// ---------------- K0: zero h ----------------
__global__ void zero_h_kernel() {
    int i = blockIdx.x * blockDim.x + threadIdx.x;
    if (i < BATCH * H) g_h[0][i] = 0.0f;
}

// ---------------- K1: fused gather + gi GEMM ----------------
// gi[m, g] = sum_k emb[ids[m], k] * W_ih[k, g]   (m = s*BATCH+b)
// M=32768, N=3072, K=1024.  CTA tile 128x128, 256 threads, 8 warps (2m x 4n).
// grid = (24 n-blocks, 256 m-blocks): n fastest so emb-gather rows reuse in L2.
__global__ void __launch_bounds__(256) gi_kernel(const int* __restrict__ ids,
                                                 const float* __restrict__ emb,
                                                 const float* __restrict__ W_ih) {
    const int nb = blockIdx.x, mb = blockIdx.y;
    const int tid = threadIdx.x;
    const int w = tid >> 5, lane = tid & 31;
    const int wm = w >> 2, wn = w & 3;        // 2 x 4 warp grid
    const int gid = lane >> 2, tig = lane & 3;

    __shared__ unsigned As[128 * 20];   // 128 rows x 16 cols, stride 20 (conflict-free)
    __shared__ unsigned Bs[16 * 136];   // 16 rows x 128 cols, stride 136 (conflict-free)
    __shared__ int ids_s[128];

    if (tid < 128) ids_s[tid] = ids[mb * 128 + tid];
    __syncthreads();

    float acc[4][4][4];
#pragma unroll
    for (int i = 0; i < 4; i++)
#pragma unroll
        for (int j = 0; j < 4; j++)
#pragma unroll
            for (int k = 0; k < 4; k++) acc[i][j][k] = 0.0f;

    for (int kt = 0; kt < H; kt += 16) {
        __syncthreads();
        // stage A (gathered): thread -> row tid/2, 8 cols
        {
            int r = tid >> 1, c0 = (tid & 1) * 8;
            const float* src = emb + (size_t)ids_s[r] * H + kt + c0;
            float4 v0 = *(const float4*)(src);
            float4 v1 = *(const float4*)(src + 4);
            unsigned* dst = &As[r * 20 + c0];
            dst[0] = f2tf(v0.x); dst[1] = f2tf(v0.y); dst[2] = f2tf(v0.z); dst[3] = f2tf(v0.w);
            dst[4] = f2tf(v1.x); dst[5] = f2tf(v1.y); dst[6] = f2tf(v1.z); dst[7] = f2tf(v1.w);
        }
        // stage B: thread -> row tid/16, 8 cols
        {
            int r = tid >> 4, c0 = (tid & 15) * 8;
            const float* src = W_ih + (size_t)(kt + r) * H3 + nb * 128 + c0;
            float4 v0 = *(const float4*)(src);
            float4 v1 = *(const float4*)(src + 4);
            unsigned* dst = &Bs[r * 136 + c0];
            dst[0] = f2tf(v0.x); dst[1] = f2tf(v0.y); dst[2] = f2tf(v0.z); dst[3] = f2tf(v0.w);
            dst[4] = f2tf(v1.x); dst[5] = f2tf(v1.y); dst[6] = f2tf(v1.z); dst[7] = f2tf(v1.w);
        }
        __syncthreads();

#pragma unroll
        for (int ks = 0; ks < 16; ks += 8) {
            unsigned a[4][4];
#pragma unroll
            for (int mt = 0; mt < 4; mt++) {
                int rb = wm * 64 + mt * 16;
                a[mt][0] = As[(rb + gid) * 20 + ks + tig];
                a[mt][1] = As[(rb + gid + 8) * 20 + ks + tig];
                a[mt][2] = As[(rb + gid) * 20 + ks + tig + 4];
                a[mt][3] = As[(rb + gid + 8) * 20 + ks + tig + 4];
            }
#pragma unroll
            for (int nt = 0; nt < 4; nt++) {
                unsigned b0 = Bs[(ks + tig) * 136 + wn * 32 + nt * 8 + gid];
                unsigned b1 = Bs[(ks + tig + 4) * 136 + wn * 32 + nt * 8 + gid];
#pragma unroll
                for (int mt = 0; mt < 4; mt++) mma8(acc[mt][nt], a[mt], b0, b1);
            }
        }
    }

    // epilogue: raw GEMM result (biases added in step kernel)
    size_t mrow0 = (size_t)mb * 128 + wm * 64;
    int colbase = nb * 128 + wn * 32;
#pragma unroll
    for (int mt = 0; mt < 4; mt++) {
        size_t m0 = mrow0 + mt * 16 + gid;
#pragma unroll
        for (int nt = 0; nt < 4; nt++) {
            int col = colbase + nt * 8 + tig * 2;
            *(float2*)(g_gi + m0 * H3 + col) = make_float2(acc[mt][nt][0], acc[mt][nt][1]);
            *(float2*)(g_gi + (m0 + 8) * H3 + col) = make_float2(acc[mt][nt][2], acc[mt][nt][3]);
        }
    }
}

// ---------------- K2: one GRU step ----------------
// 128 CTAs, CTA c owns n-columns [c*8, c*8+8) across the 3 gates (r,z,n).
// gh chunk = h_prev[64,1024] @ W_hh[:, {c8, H+c8, 2H+c8}]  -> [64, 24]
// 8 warps = 4 m-tiles x 2 k-halves, tf32 mma; partial sums combined via smem,
// then fp32 gate math and h_new write.
__global__ void __launch_bounds__(256) step_kernel(const float* __restrict__ W_hh,
                                                   const float* __restrict__ b_ih,
                                                   const float* __restrict__ b_hh,
                                                   int s) {
    const float* hin = g_h[s & 1];
    float* hout = g_h[(s + 1) & 1];
    const float* gi = g_gi + (size_t)s * BATCH * H3;

    const int c = blockIdx.x;               // 0..127
    const int tid = threadIdx.x;
    const int w = tid >> 5, lane = tid & 31;
    const int gid = lane >> 2, tig = lane & 3;
    const int mt = w & 3, kh = w >> 2;      // m-tile, k-half

    __shared__ unsigned As[2][64 * 36];     // [kh][row][32 cols, stride 36]
    __shared__ unsigned Bs[64 * 40];        // [kh*32+kk][gate*8+l], stride 40
    __shared__ float ghs[2][64 * 24];       // per-k-half partial gh

    float acc[3][4];
#pragma unroll
    for (int i = 0; i < 3; i++)
#pragma unroll
        for (int j = 0; j < 4; j++) acc[i][j] = 0.0f;

    for (int kt = 0; kt < 512; kt += 32) {
        __syncthreads();
        // stage A: 2 halves x 64 rows x 32 cols (h_prev), tf32-rounded
        {
            int half = tid >> 7;
            int r = (tid >> 1) & 63;
            int c0 = (tid & 1) * 16;
            const float* src = hin + r * H + half * 512 + kt + c0;
            unsigned* dst = &As[half][r * 36 + c0];
#pragma unroll
            for (int i = 0; i < 4; i++) {
                float4 v = *(const float4*)(src + i * 4);
                dst[i * 4 + 0] = f2tf(v.x); dst[i * 4 + 1] = f2tf(v.y);
                dst[i * 4 + 2] = f2tf(v.z); dst[i * 4 + 3] = f2tf(v.w);
            }
        }
        // stage B: 64 (k-rows, both halves) x 24 cols of W_hh
#pragma unroll
        for (int rep = 0; rep < 6; rep++) {
            int e = rep * 256 + tid;        // 0..1535
            int kk = e / 24;
            int rem = e - kk * 24;
            int g = rem >> 3, l = rem & 7;
            int half = kk >> 5;
            int krow = half * 512 + kt + (kk & 31);
            Bs[kk * 40 + g * 8 + l] = f2tf(W_hh[(size_t)krow * H3 + g * H + c * 8 + l]);
        }
        __syncthreads();

#pragma unroll
        for (int ks = 0; ks < 32; ks += 8) {
            unsigned a[4];
            int rb = mt * 16;
            a[0] = As[kh][(rb + gid) * 36 + ks + tig];
            a[1] = As[kh][(rb + gid + 8) * 36 + ks + tig];
            a[2] = As[kh][(rb + gid) * 36 + ks + tig + 4];
            a[3] = As[kh][(rb + gid + 8) * 36 + ks + tig + 4];
#pragma unroll
            for (int nt = 0; nt < 3; nt++) {
                unsigned b0 = Bs[(kh * 32 + ks + tig) * 40 + nt * 8 + gid];
                unsigned b1 = Bs[(kh * 32 + ks + tig + 4) * 40 + nt * 8 + gid];
                mma8(acc[nt], a, b0, b1);
            }
        }
    }

    // write partial gh fragments
    {
        int r0 = mt * 16 + gid;
#pragma unroll
        for (int nt = 0; nt < 3; nt++) {
            ghs[kh][r0 * 24 + nt * 8 + tig * 2 + 0] = acc[nt][0];
            ghs[kh][r0 * 24 + nt * 8 + tig * 2 + 1] = acc[nt][1];
            ghs[kh][(r0 + 8) * 24 + nt * 8 + tig * 2 + 0] = acc[nt][2];
            ghs[kh][(r0 + 8) * 24 + nt * 8 + tig * 2 + 1] = acc[nt][3];
        }
    }
    __syncthreads();

    // gate math: 512 (row, j) pairs -> 2 per thread
#pragma unroll
    for (int e = tid; e < 512; e += 256) {
        int row = e >> 3, j = e & 7;
        int col = c * 8 + j;
        float ghr = ghs[0][row * 24 + j]      + ghs[1][row * 24 + j]      + b_hh[col];
        float ghz = ghs[0][row * 24 + 8 + j]  + ghs[1][row * 24 + 8 + j]  + b_hh[H + col];
        float ghn = ghs[0][row * 24 + 16 + j] + ghs[1][row * 24 + 16 + j] + b_hh[2 * H + col];
        const float* gip = gi + (size_t)row * H3;
        float ir = gip[col]         + b_ih[col];
        float iz = gip[H + col]     + b_ih[H + col];
        float in_ = gip[2 * H + col] + b_ih[2 * H + col];
        float r = 1.0f / (1.0f + __expf(-(ir + ghr)));
        float z = 1.0f / (1.0f + __expf(-(iz + ghz)));
        float n = tanhf(in_ + r * ghn);
        float hp = hin[row * H + col];
        hout[row * H + col] = (1.0f - z) * n + z * hp;
    }
}

// ---------------- K3: decode + fc ----------------
__global__ void dec_kernel(const float* __restrict__ W_dec, const float* __restrict__ b_dec,
                           const float* __restrict__ W_fc, const float* __restrict__ b_fc,
                           float* __restrict__ out) {
    int b = blockIdx.x;        // 0..63
    int tid = threadIdx.x;     // 128 threads
    __shared__ float hs[H];
    __shared__ float ds[100];
    const float* hrow = g_h[0] + b * H;   // after 512 steps final h is in buffer 0
    for (int i = tid; i < H; i += 128) hs[i] = hrow[i];
    __syncthreads();
    if (tid < 100) {
        float a = b_dec[tid];
        for (int k = 0; k < H; k++) a += hs[k] * W_dec[k * 100 + tid];
        ds[tid] = fmaxf(a, 0.0f);
    }
    __syncthreads();
    if (tid < 2) {
        float a = b_fc[tid];
        for (int j = 0; j < 100; j++) a += ds[j] * W_fc[j * 2 + tid];
        out[b * 2 + tid] = a;
    }
}

// ---------------- launch ----------------
extern "C" void kernel_launch(void* const* d_in, const int* in_sizes, int n_in,
                              void* d_out, int out_size) {
    const int* ids = (const int*)d_in[0];
    const float* emb = (const float*)d_in[1];
    const float* W_ih = (const float*)d_in[2];
    const float* W_hh = (const float*)d_in[3];
    const float* b_ih = (const float*)d_in[4];
    const float* b_hh = (const float*)d_in[5];
    const float* W_dec = (const float*)d_in[6];
    const float* b_dec = (const float*)d_in[7];
    const float* W_fc = (const float*)d_in[8];
    const float* b_fc = (const float*)d_in[9];
    float* out = (float*)d_out;

    zero_h_kernel<<<256, 256>>>();

    dim3 g1(24, 256);
    gi_kernel<<<g1, 256>>>(ids, emb, W_ih);

    for (int s = 0; s < SEQ; s++)
        step_kernel<<<128, 256>>>(W_hh, b_ih, b_hh, s);

    dec_kernel<<<64, 128>>>(W_dec, b_dec, W_fc, b_fc, out);
}

// round 3
// speedup vs baseline: 1.9800x; 1.9800x over previous
#include <cuda_runtime.h>
#include <cstdint>

#define SEQ   512
#define BATCH 64
#define H     1024
#define H3    3072
#define NCTA  128

// ---------------- device scratch (no cudaMalloc allowed) ----------------
__device__ float    g_gi[(size_t)SEQ * BATCH * H3];  // encoded @ W_ih (no bias)
__device__ float    g_h[2][BATCH * H];               // h ping-pong (fp32)
__device__ unsigned g_htf[2][BATCH * H];             // h ping-pong (tf32 bits, rna-rounded)
__device__ unsigned g_bar;                           // grid barrier arrive counter
__device__ unsigned g_gen;                           // grid barrier generation

// ---------------- helpers ----------------
__device__ __forceinline__ unsigned f2tf(float x) {
    unsigned r;
    asm("cvt.rna.tf32.f32 %0, %1;" : "=r"(r) : "f"(x));
    return r;
}

__device__ __forceinline__ void mma8(float c[4], const unsigned a[4],
                                     unsigned b0, unsigned b1) {
    asm volatile(
        "mma.sync.aligned.m16n8k8.row.col.f32.tf32.tf32.f32 "
        "{%0,%1,%2,%3},{%4,%5,%6,%7},{%8,%9},{%0,%1,%2,%3};"
        : "+f"(c[0]), "+f"(c[1]), "+f"(c[2]), "+f"(c[3])
        : "r"(a[0]), "r"(a[1]), "r"(a[2]), "r"(a[3]), "r"(b0), "r"(b1));
}

#define CP_ASYNC16(dst, src) \
    asm volatile("cp.async.cg.shared.global [%0], [%1], 16;" :: "r"(dst), "l"(src))
#define CP_COMMIT() asm volatile("cp.async.commit_group;" ::: "memory")
#define CP_WAIT1()  asm volatile("cp.async.wait_group 1;" ::: "memory")
#define CP_WAIT0()  asm volatile("cp.async.wait_group 0;" ::: "memory")

// ---------------- K0: init (zero h, reset barrier) ----------------
__global__ void init_kernel() {
    int i = blockIdx.x * blockDim.x + threadIdx.x;
    if (i < BATCH * H) { g_h[0][i] = 0.0f; g_htf[0][i] = 0u; }
    if (i == 0) { g_bar = 0u; g_gen = 0u; }
}

// ---------------- K1: fused gather + gi GEMM (unchanged from R1) ----------------
__global__ void __launch_bounds__(256) gi_kernel(const int* __restrict__ ids,
                                                 const float* __restrict__ emb,
                                                 const float* __restrict__ W_ih) {
    const int nb = blockIdx.x, mb = blockIdx.y;
    const int tid = threadIdx.x;
    const int w = tid >> 5, lane = tid & 31;
    const int wm = w >> 2, wn = w & 3;
    const int gid = lane >> 2, tig = lane & 3;

    __shared__ unsigned As[128 * 20];
    __shared__ unsigned Bs[16 * 136];
    __shared__ int ids_s[128];

    if (tid < 128) ids_s[tid] = ids[mb * 128 + tid];
    __syncthreads();

    float acc[4][4][4];
#pragma unroll
    for (int i = 0; i < 4; i++)
#pragma unroll
        for (int j = 0; j < 4; j++)
#pragma unroll
            for (int k = 0; k < 4; k++) acc[i][j][k] = 0.0f;

    for (int kt = 0; kt < H; kt += 16) {
        __syncthreads();
        {
            int r = tid >> 1, c0 = (tid & 1) * 8;
            const float* src = emb + (size_t)ids_s[r] * H + kt + c0;
            float4 v0 = *(const float4*)(src);
            float4 v1 = *(const float4*)(src + 4);
            unsigned* dst = &As[r * 20 + c0];
            dst[0] = f2tf(v0.x); dst[1] = f2tf(v0.y); dst[2] = f2tf(v0.z); dst[3] = f2tf(v0.w);
            dst[4] = f2tf(v1.x); dst[5] = f2tf(v1.y); dst[6] = f2tf(v1.z); dst[7] = f2tf(v1.w);
        }
        {
            int r = tid >> 4, c0 = (tid & 15) * 8;
            const float* src = W_ih + (size_t)(kt + r) * H3 + nb * 128 + c0;
            float4 v0 = *(const float4*)(src);
            float4 v1 = *(const float4*)(src + 4);
            unsigned* dst = &Bs[r * 136 + c0];
            dst[0] = f2tf(v0.x); dst[1] = f2tf(v0.y); dst[2] = f2tf(v0.z); dst[3] = f2tf(v0.w);
            dst[4] = f2tf(v1.x); dst[5] = f2tf(v1.y); dst[6] = f2tf(v1.z); dst[7] = f2tf(v1.w);
        }
        __syncthreads();

#pragma unroll
        for (int ks = 0; ks < 16; ks += 8) {
            unsigned a[4][4];
#pragma unroll
            for (int mt = 0; mt < 4; mt++) {
                int rb = wm * 64 + mt * 16;
                a[mt][0] = As[(rb + gid) * 20 + ks + tig];
                a[mt][1] = As[(rb + gid + 8) * 20 + ks + tig];
                a[mt][2] = As[(rb + gid) * 20 + ks + tig + 4];
                a[mt][3] = As[(rb + gid + 8) * 20 + ks + tig + 4];
            }
#pragma unroll
            for (int nt = 0; nt < 4; nt++) {
                unsigned b0 = Bs[(ks + tig) * 136 + wn * 32 + nt * 8 + gid];
                unsigned b1 = Bs[(ks + tig + 4) * 136 + wn * 32 + nt * 8 + gid];
#pragma unroll
                for (int mt = 0; mt < 4; mt++) mma8(acc[mt][nt], a[mt], b0, b1);
            }
        }
    }

    size_t mrow0 = (size_t)mb * 128 + wm * 64;
    int colbase = nb * 128 + wn * 32;
#pragma unroll
    for (int mt = 0; mt < 4; mt++) {
        size_t m0 = mrow0 + mt * 16 + gid;
#pragma unroll
        for (int nt = 0; nt < 4; nt++) {
            int col = colbase + nt * 8 + tig * 2;
            *(float2*)(g_gi + m0 * H3 + col) = make_float2(acc[mt][nt][0], acc[mt][nt][1]);
            *(float2*)(g_gi + (m0 + 8) * H3 + col) = make_float2(acc[mt][nt][2], acc[mt][nt][3]);
        }
    }
}

// ---------------- K2: persistent GRU recurrence ----------------
// 128 CTAs x 256 threads, all co-resident (grid < 148 SMs). CTA c owns output
// cols [c*8, c*8+8) across gates (r,z,n): a 1024x24 W_hh slice, held in smem
// as tf32 for all 512 steps. Per step: warp-private double-buffered cp.async
// of the tf32 h shadow buffer, mma, smem reduction, gate math, grid barrier.
//
// smem words: Ws 1024*24 = 24576 | As 8 warps * 2 bufs * 576 = 9216 | ghs 3072
// total 36864 words = 147456 B (dynamic).
#define WS_WORDS   (1024 * 24)
#define AS_WORDS_W 576                  // per (warp,buf): 16 rows * stride 36
#define AS_WORDS   (8 * 2 * AS_WORDS_W)
#define GH_WORDS   (2 * 64 * 24)
#define SMEM_BYTES ((WS_WORDS + AS_WORDS + GH_WORDS) * 4)

__global__ void __launch_bounds__(256, 1) gru_persist_kernel(
    const float* __restrict__ W_hh,
    const float* __restrict__ b_ih,
    const float* __restrict__ b_hh) {
    extern __shared__ unsigned sm[];
    unsigned* Ws = sm;                          // [1024][24], stride 24 (conflict-free)
    unsigned* As = sm + WS_WORDS;               // [warp][buf][16*36]
    float* ghs = (float*)(sm + WS_WORDS + AS_WORDS);  // [kh][64][24]

    const int c = blockIdx.x;
    const int tid = threadIdx.x;
    const int w = tid >> 5, lane = tid & 31;
    const int gid = lane >> 2, tig = lane & 3;
    const int mt = w & 3, kh = w >> 2;          // warp = m-tile x k-half

    // smem u32 base address of this warp's two A staging buffers
    unsigned as_base;
    {
        unsigned gen = (unsigned)__cvta_generic_to_shared(As + w * 2 * AS_WORDS_W);
        as_base = gen;
    }

    // ---- one-time W_hh slice preload (rna tf32) ----
    for (int idx = tid; idx < WS_WORDS; idx += 256) {
        int kk = idx / 24;
        int rem = idx - kk * 24;
        int g = rem >> 3, l = rem & 7;
        Ws[idx] = f2tf(W_hh[(size_t)kk * H3 + g * H + c * 8 + l]);
    }

    // ---- per-thread gate-phase constants ----
    const int j = tid & 7;                      // col within CTA's 8
    const int col = c * 8 + j;
    const int r0 = tid >> 3;                    // rows r0 and r0+32
    const float bir = b_ih[col],     biz = b_ih[H + col],     bin = b_ih[2 * H + col];
    const float bhr = b_hh[col],     bhz = b_hh[H + col],     bhn = b_hh[2 * H + col];

    __syncthreads();

    for (int s = 0; s < SEQ; s++) {
        const float*    hin   = g_h[s & 1];
        float*          hout  = g_h[(s + 1) & 1];
        const unsigned* htf   = g_htf[s & 1];
        unsigned*       htfo  = g_htf[(s + 1) & 1];
        const float*    gi    = g_gi + (size_t)s * BATCH * H3;

        // prefetch gi + h_prev for the gate phase (hidden behind mma)
        const float* gp0 = gi + (size_t)r0 * H3;
        const float* gp1 = gi + (size_t)(r0 + 32) * H3;
        float ir0 = gp0[col], iz0 = gp0[H + col], in0 = gp0[2 * H + col];
        float ir1 = gp1[col], iz1 = gp1[H + col], in1 = gp1[2 * H + col];
        float hp0 = hin[r0 * H + col];
        float hp1 = hin[(r0 + 32) * H + col];

        float acc[3][4];
#pragma unroll
        for (int i = 0; i < 3; i++)
#pragma unroll
            for (int q = 0; q < 4; q++) acc[i][q] = 0.0f;

        // ---- stage iter 0 ----
        {
#pragma unroll
            for (int rep = 0; rep < 4; rep++) {
                int chunk = rep * 32 + lane;
                int row16 = chunk >> 3;
                int c0 = (chunk & 7) * 4;
                const unsigned* src = htf + (mt * 16 + row16) * H + kh * 512 + c0;
                CP_ASYNC16(as_base + (unsigned)(row16 * 36 + c0) * 4u, src);
            }
            CP_COMMIT();
        }

        // ---- k-loop: 16 iters x 64 k-cols (32 per half), warp-private ----
        for (int it = 0; it < 16; it++) {
            const int buf = it & 1;
            if (it < 15) {
                int kt = (it + 1) * 32;
                unsigned dst_base = as_base + (unsigned)((buf ^ 1) * AS_WORDS_W) * 4u;
#pragma unroll
                for (int rep = 0; rep < 4; rep++) {
                    int chunk = rep * 32 + lane;
                    int row16 = chunk >> 3;
                    int c0 = (chunk & 7) * 4;
                    const unsigned* src = htf + (mt * 16 + row16) * H + kh * 512 + kt + c0;
                    CP_ASYNC16(dst_base + (unsigned)(row16 * 36 + c0) * 4u, src);
                }
                CP_COMMIT();
                CP_WAIT1();
            } else {
                CP_WAIT0();
            }
            __syncwarp();

            const unsigned* Ab = As + (w * 2 + buf) * AS_WORDS_W;
            const int kbase = kh * 512 + it * 32;
#pragma unroll
            for (int ks = 0; ks < 32; ks += 8) {
                unsigned a[4];
                a[0] = Ab[gid * 36 + ks + tig];
                a[1] = Ab[(gid + 8) * 36 + ks + tig];
                a[2] = Ab[gid * 36 + ks + tig + 4];
                a[3] = Ab[(gid + 8) * 36 + ks + tig + 4];
                const int kr = (kbase + ks + tig) * 24;
#pragma unroll
                for (int nt = 0; nt < 3; nt++) {
                    unsigned b0 = Ws[kr + nt * 8 + gid];
                    unsigned b1 = Ws[kr + 96 + nt * 8 + gid];   // +4 k-rows * 24
                    mma8(acc[nt], a, b0, b1);
                }
            }
        }

        // ---- reduce the two k-halves via smem ----
        {
            int rr = mt * 16 + gid;
            float* gh = ghs + kh * (64 * 24);
#pragma unroll
            for (int nt = 0; nt < 3; nt++) {
                gh[rr * 24 + nt * 8 + tig * 2 + 0] = acc[nt][0];
                gh[rr * 24 + nt * 8 + tig * 2 + 1] = acc[nt][1];
                gh[(rr + 8) * 24 + nt * 8 + tig * 2 + 0] = acc[nt][2];
                gh[(rr + 8) * 24 + nt * 8 + tig * 2 + 1] = acc[nt][3];
            }
        }
        __syncthreads();

        // ---- gate math: each thread handles (r0, j) and (r0+32, j) ----
        {
            float ghr = ghs[r0 * 24 + j] + ghs[64 * 24 + r0 * 24 + j] + bhr;
            float ghz = ghs[r0 * 24 + 8 + j] + ghs[64 * 24 + r0 * 24 + 8 + j] + bhz;
            float ghn = ghs[r0 * 24 + 16 + j] + ghs[64 * 24 + r0 * 24 + 16 + j] + bhn;
            float r = 1.0f / (1.0f + __expf(-(ir0 + bir + ghr)));
            float z = 1.0f / (1.0f + __expf(-(iz0 + biz + ghz)));
            float n = tanhf(in0 + bin + r * ghn);
            float hn = (1.0f - z) * n + z * hp0;
            hout[r0 * H + col] = hn;
            htfo[r0 * H + col] = f2tf(hn);

            int r1 = r0 + 32;
            ghr = ghs[r1 * 24 + j] + ghs[64 * 24 + r1 * 24 + j] + bhr;
            ghz = ghs[r1 * 24 + 8 + j] + ghs[64 * 24 + r1 * 24 + 8 + j] + bhz;
            ghn = ghs[r1 * 24 + 16 + j] + ghs[64 * 24 + r1 * 24 + 16 + j] + bhn;
            r = 1.0f / (1.0f + __expf(-(ir1 + bir + ghr)));
            z = 1.0f / (1.0f + __expf(-(iz1 + biz + ghz)));
            n = tanhf(in1 + bin + r * ghn);
            hn = (1.0f - z) * n + z * hp1;
            hout[r1 * H + col] = hn;
            htfo[r1 * H + col] = f2tf(hn);
        }

        // ---- grid barrier (all CTAs co-resident; monotonic counters) ----
        __syncthreads();
        if (tid == 0) {
            __threadfence();
            unsigned target = (unsigned)s + 1u;
            unsigned v = atomicAdd(&g_bar, 1u) + 1u;
            if (v == (unsigned)NCTA * target) {
                atomicExch(&g_gen, target);
            } else {
                while (*(volatile unsigned*)&g_gen < target) {}
            }
            __threadfence();
        }
        __syncthreads();
    }
}

// ---------------- K3: decode + fc ----------------
__global__ void dec_kernel(const float* __restrict__ W_dec, const float* __restrict__ b_dec,
                           const float* __restrict__ W_fc, const float* __restrict__ b_fc,
                           float* __restrict__ out) {
    int b = blockIdx.x;
    int tid = threadIdx.x;
    __shared__ float hs[H];
    __shared__ float ds[100];
    const float* hrow = g_h[0] + b * H;   // SEQ even -> final h in buffer 0
    for (int i = tid; i < H; i += 128) hs[i] = hrow[i];
    __syncthreads();
    if (tid < 100) {
        float a = b_dec[tid];
        for (int k = 0; k < H; k++) a += hs[k] * W_dec[k * 100 + tid];
        ds[tid] = fmaxf(a, 0.0f);
    }
    __syncthreads();
    if (tid < 2) {
        float a = b_fc[tid];
        for (int jj = 0; jj < 100; jj++) a += ds[jj] * W_fc[jj * 2 + tid];
        out[b * 2 + tid] = a;
    }
}

// ---------------- launch ----------------
extern "C" void kernel_launch(void* const* d_in, const int* in_sizes, int n_in,
                              void* d_out, int out_size) {
    const int* ids = (const int*)d_in[0];
    const float* emb = (const float*)d_in[1];
    const float* W_ih = (const float*)d_in[2];
    const float* W_hh = (const float*)d_in[3];
    const float* b_ih = (const float*)d_in[4];
    const float* b_hh = (const float*)d_in[5];
    const float* W_dec = (const float*)d_in[6];
    const float* b_dec = (const float*)d_in[7];
    const float* W_fc = (const float*)d_in[8];
    const float* b_fc = (const float*)d_in[9];
    float* out = (float*)d_out;

    static bool attr_set = false;
    if (!attr_set) {
        cudaFuncSetAttribute(gru_persist_kernel,
                             cudaFuncAttributeMaxDynamicSharedMemorySize, SMEM_BYTES);
        attr_set = true;
    }

    init_kernel<<<256, 256>>>();

    dim3 g1(24, 256);
    gi_kernel<<<g1, 256>>>(ids, emb, W_ih);

    gru_persist_kernel<<<NCTA, 256, SMEM_BYTES>>>(W_hh, b_ih, b_hh);

    dec_kernel<<<64, 128>>>(W_dec, b_dec, W_fc, b_fc, out);
}

// round 5
// speedup vs baseline: 2.3478x; 1.1858x over previous
#include <cuda_runtime.h>
#include <cstdint>

#define SEQ   512
#define BATCH 64
#define H     1024
#define H3    3072
#define NCTA  128

// ---------------- device scratch (no cudaMalloc allowed) ----------------
__device__ float    g_gi[(size_t)SEQ * BATCH * H3];  // encoded @ W_ih (no bias)
__device__ float    g_h[2][BATCH * H];               // h ping-pong (fp32)
__device__ unsigned g_htf[2][BATCH * H];             // h ping-pong (tf32 bits)
__device__ unsigned g_bar;                           // grid barrier arrive counter
__device__ unsigned g_gen;                           // grid barrier generation

// ---------------- helpers ----------------
__device__ __forceinline__ unsigned f2tf(float x) {
    unsigned r;
    asm("cvt.rna.tf32.f32 %0, %1;" : "=r"(r) : "f"(x));
    return r;
}

__device__ __forceinline__ void mma8(float c[4], const unsigned a[4],
                                     unsigned b0, unsigned b1) {
    asm volatile(
        "mma.sync.aligned.m16n8k8.row.col.f32.tf32.tf32.f32 "
        "{%0,%1,%2,%3},{%4,%5,%6,%7},{%8,%9},{%0,%1,%2,%3};"
        : "+f"(c[0]), "+f"(c[1]), "+f"(c[2]), "+f"(c[3])
        : "r"(a[0]), "r"(a[1]), "r"(a[2]), "r"(a[3]), "r"(b0), "r"(b1));
}

#define CP_ASYNC16(dst, src) \
    asm volatile("cp.async.cg.shared.global [%0], [%1], 16;" :: "r"(dst), "l"(src))
#define CP_COMMIT()  asm volatile("cp.async.commit_group;" ::: "memory")
#define CP_WAIT(n)   asm volatile("cp.async.wait_group %0;" :: "n"(n) : "memory")

__device__ __forceinline__ unsigned atom_add_release(unsigned* p, unsigned v) {
    unsigned old;
    asm volatile("atom.add.release.gpu.u32 %0, [%1], %2;"
                 : "=r"(old) : "l"(p), "r"(v) : "memory");
    return old;
}
__device__ __forceinline__ unsigned ld_acquire(const unsigned* p) {
    unsigned v;
    asm volatile("ld.acquire.gpu.u32 %0, [%1];" : "=r"(v) : "l"(p) : "memory");
    return v;
}
__device__ __forceinline__ void st_release(unsigned* p, unsigned v) {
    asm volatile("st.release.gpu.u32 [%0], %1;" :: "l"(p), "r"(v) : "memory");
}
__device__ __forceinline__ float ldcg(const float* p) {
    float v;
    asm volatile("ld.global.cg.f32 %0, [%1];" : "=f"(v) : "l"(p));
    return v;
}

__device__ __forceinline__ float sigm(float x) { return 1.0f / (1.0f + __expf(-x)); }
__device__ __forceinline__ float tanh_fast(float x) {
    float e = __expf(2.0f * x);
    return 1.0f - 2.0f / (e + 1.0f);
}

// ---------------- K0: init ----------------
__global__ void init_kernel() {
    int i = blockIdx.x * blockDim.x + threadIdx.x;
    if (i < BATCH * H) { g_h[0][i] = 0.0f; g_htf[0][i] = 0u; }
    if (i == 0) { g_bar = 0u; g_gen = 0u; }
}

// ---------------- K1: fused gather + gi GEMM (cp.async double-buffered) ----------------
// M=32768, N=3072, K=1024. CTA tile 128x128, k-tile 32, 256 threads (2m x 4n warps).
#define GI_AS_BUF (128 * 36)            // fp32 words per A buffer (stride 36)
#define GI_BS_BUF (32 * 136)            // fp32 words per B buffer (stride 136)
#define GI_SMEM_BYTES ((2 * GI_AS_BUF + 2 * GI_BS_BUF) * 4)

__global__ void __launch_bounds__(256) gi_kernel(const int* __restrict__ ids,
                                                 const float* __restrict__ emb,
                                                 const float* __restrict__ W_ih) {
    extern __shared__ float gsm[];
    float* As = gsm;                     // [2][128][36]
    float* Bs = gsm + 2 * GI_AS_BUF;     // [2][32][136]
    __shared__ int ids_s[128];

    const int nb = blockIdx.x, mb = blockIdx.y;
    const int tid = threadIdx.x;
    const int w = tid >> 5, lane = tid & 31;
    const int wm = w >> 2, wn = w & 3;
    const int gid = lane >> 2, tig = lane & 3;

    if (tid < 128) ids_s[tid] = ids[mb * 128 + tid];
    __syncthreads();

    const unsigned as_smem = (unsigned)__cvta_generic_to_shared(As);
    const unsigned bs_smem = (unsigned)__cvta_generic_to_shared(Bs);

    const int a_row0 = tid >> 3;         // 0..31
    const int a_c0 = (tid & 7) * 4;      // word col 0..28
    const int b_r0 = tid >> 5;           // 0..7
    const int b_c0 = (tid & 31) * 4;     // word col 0..124

    auto stageA = [&](int buf, int kt) {
#pragma unroll
        for (int rep = 0; rep < 4; rep++) {
            int row = rep * 32 + a_row0;
            const float* src = emb + (size_t)ids_s[row] * H + kt + a_c0;
            CP_ASYNC16(as_smem + (unsigned)(buf * GI_AS_BUF + row * 36 + a_c0) * 4u, src);
        }
    };
    auto stageB = [&](int buf, int kt) {
#pragma unroll
        for (int rep = 0; rep < 4; rep++) {
            int r = rep * 8 + b_r0;
            const float* src = W_ih + (size_t)(kt + r) * H3 + nb * 128 + b_c0;
            CP_ASYNC16(bs_smem + (unsigned)(buf * GI_BS_BUF + r * 136 + b_c0) * 4u, src);
        }
    };

    float acc[4][4][4];
#pragma unroll
    for (int i = 0; i < 4; i++)
#pragma unroll
        for (int j = 0; j < 4; j++)
#pragma unroll
            for (int k = 0; k < 4; k++) acc[i][j][k] = 0.0f;

    stageA(0, 0); stageB(0, 0); CP_COMMIT();

    for (int t = 0; t < 32; t++) {
        const int buf = t & 1;
        __syncthreads();                  // buf^1 free (compute t-1 done everywhere)
        if (t < 31) {
            stageA(buf ^ 1, (t + 1) * 32);
            stageB(buf ^ 1, (t + 1) * 32);
            CP_COMMIT();
            CP_WAIT(1);
        } else {
            CP_WAIT(0);
        }
        __syncthreads();

        const float* Ab = As + buf * GI_AS_BUF;
        const float* Bb = Bs + buf * GI_BS_BUF;
#pragma unroll
        for (int ks = 0; ks < 32; ks += 8) {
            unsigned a[4][4];
#pragma unroll
            for (int mt = 0; mt < 4; mt++) {
                int rb = wm * 64 + mt * 16;
                a[mt][0] = f2tf(Ab[(rb + gid) * 36 + ks + tig]);
                a[mt][1] = f2tf(Ab[(rb + gid + 8) * 36 + ks + tig]);
                a[mt][2] = f2tf(Ab[(rb + gid) * 36 + ks + tig + 4]);
                a[mt][3] = f2tf(Ab[(rb + gid + 8) * 36 + ks + tig + 4]);
            }
#pragma unroll
            for (int nt = 0; nt < 4; nt++) {
                unsigned b0 = f2tf(Bb[(ks + tig) * 136 + wn * 32 + nt * 8 + gid]);
                unsigned b1 = f2tf(Bb[(ks + tig + 4) * 136 + wn * 32 + nt * 8 + gid]);
#pragma unroll
                for (int mt = 0; mt < 4; mt++) mma8(acc[mt][nt], a[mt], b0, b1);
            }
        }
    }

    size_t mrow0 = (size_t)mb * 128 + wm * 64;
    int colbase = nb * 128 + wn * 32;
#pragma unroll
    for (int mt = 0; mt < 4; mt++) {
        size_t m0 = mrow0 + mt * 16 + gid;
#pragma unroll
        for (int nt = 0; nt < 4; nt++) {
            int col = colbase + nt * 8 + tig * 2;
            *(float2*)(g_gi + m0 * H3 + col) = make_float2(acc[mt][nt][0], acc[mt][nt][1]);
            *(float2*)(g_gi + (m0 + 8) * H3 + col) = make_float2(acc[mt][nt][2], acc[mt][nt][3]);
        }
    }
}

// ---------------- K2: persistent GRU recurrence ----------------
// 128 CTAs x 256 threads. CTA c owns cols [c*8, c*8+8) of gates (r,z,n).
// W_hh slice resident in smem as tf32; per step: 4-deep warp-private cp.async
// pipeline over the tf32 h shadow, tf32 mma, smem k-half reduce, gate math,
// release/acquire grid barrier (no L1 flush; cross-CTA h reads are L2-only).
#define WS_WORDS   (1024 * 24)
#define AS_WORDS_W 576                  // per (warp,buf): 16 rows x stride 36
#define N_BUF      4
#define AS_WORDS   (8 * N_BUF * AS_WORDS_W)
#define GH_WORDS   (2 * 64 * 24)
#define SMEM_BYTES ((WS_WORDS + AS_WORDS + GH_WORDS) * 4)

__global__ void __launch_bounds__(256, 1) gru_persist_kernel(
    const float* __restrict__ W_hh,
    const float* __restrict__ b_ih,
    const float* __restrict__ b_hh) {
    extern __shared__ unsigned sm[];
    unsigned* Ws = sm;                                  // [1024][24]
    unsigned* As = sm + WS_WORDS;                       // [warp][4][16*36]
    float* ghs = (float*)(sm + WS_WORDS + AS_WORDS);    // [kh][64][24]

    const int c = blockIdx.x;
    const int tid = threadIdx.x;
    const int w = tid >> 5, lane = tid & 31;
    const int gid = lane >> 2, tig = lane & 3;
    const int mt = w & 3, kh = w >> 2;

    const unsigned as_base =
        (unsigned)__cvta_generic_to_shared(As + w * N_BUF * AS_WORDS_W);
    const int lr = lane >> 3;            // 0..3
    const int cw = (lane & 7) * 4;       // word col within 32

    // one-time W_hh slice preload (rna tf32)
    for (int idx = tid; idx < WS_WORDS; idx += 256) {
        int kk = idx / 24;
        int rem = idx - kk * 24;
        int g = rem >> 3, l = rem & 7;
        Ws[idx] = f2tf(W_hh[(size_t)kk * H3 + g * H + c * 8 + l]);
    }

    const int j = tid & 7;
    const int col = c * 8 + j;
    const int r0 = tid >> 3;
    const float bir = b_ih[col], biz = b_ih[H + col], bin = b_ih[2 * H + col];
    const float bhr = b_hh[col], bhz = b_hh[H + col], bhn = b_hh[2 * H + col];

    __syncthreads();

    for (int s = 0; s < SEQ; s++) {
        const float*    hin  = g_h[s & 1];
        float*          hout = g_h[(s + 1) & 1];
        const unsigned* htf  = g_htf[s & 1];
        unsigned*       htfo = g_htf[(s + 1) & 1];
        const float*    gi   = g_gi + (size_t)s * BATCH * H3;

        const unsigned* hsrc = htf + (mt * 16) * H + kh * 512 + cw;

        // stage pipeline: 3 tiles ahead  (dst includes the lane col offset cw!)
#pragma unroll
        for (int p = 0; p < 3; p++) {
            unsigned dst = as_base + (unsigned)(p * AS_WORDS_W) * 4u;
#pragma unroll
            for (int rep = 0; rep < 4; rep++) {
                int row = rep * 4 + lr;
                CP_ASYNC16(dst + (unsigned)(row * 36 + cw) * 4u, hsrc + row * H + p * 32);
            }
            CP_COMMIT();
        }

        // gate-phase prefetch (independent; hides DRAM/L2 latency behind mma)
        const float* gp0 = gi + (size_t)r0 * H3;
        const float* gp1 = gi + (size_t)(r0 + 32) * H3;
        float ir0 = gp0[col], iz0 = gp0[H + col], in0 = gp0[2 * H + col];
        float ir1 = gp1[col], iz1 = gp1[H + col], in1 = gp1[2 * H + col];
        float hp0 = ldcg(hin + r0 * H + col);
        float hp1 = ldcg(hin + (r0 + 32) * H + col);

        float acc[3][4];
#pragma unroll
        for (int i = 0; i < 3; i++)
#pragma unroll
            for (int q = 0; q < 4; q++) acc[i][q] = 0.0f;

#pragma unroll
        for (int it = 0; it < 16; it++) {
            if (it < 13) {
                int p = it + 3;
                unsigned dst = as_base + (unsigned)((p & 3) * AS_WORDS_W) * 4u;
#pragma unroll
                for (int rep = 0; rep < 4; rep++) {
                    int row = rep * 4 + lr;
                    CP_ASYNC16(dst + (unsigned)(row * 36 + cw) * 4u,
                               hsrc + row * H + p * 32);
                }
                CP_COMMIT();
                CP_WAIT(3);
            } else if (it == 13) CP_WAIT(2);
            else if (it == 14) CP_WAIT(1);
            else CP_WAIT(0);
            __syncwarp();

            const unsigned* Ab = As + (w * N_BUF + (it & 3)) * AS_WORDS_W;
            const int kbase = kh * 512 + it * 32;
#pragma unroll
            for (int ks = 0; ks < 32; ks += 8) {
                unsigned a[4];
                a[0] = Ab[gid * 36 + ks + tig];
                a[1] = Ab[(gid + 8) * 36 + ks + tig];
                a[2] = Ab[gid * 36 + ks + tig + 4];
                a[3] = Ab[(gid + 8) * 36 + ks + tig + 4];
                const int kr = (kbase + ks + tig) * 24;
#pragma unroll
                for (int nt = 0; nt < 3; nt++) {
                    unsigned b0 = Ws[kr + nt * 8 + gid];
                    unsigned b1 = Ws[kr + 96 + nt * 8 + gid];
                    mma8(acc[nt], a, b0, b1);
                }
            }
        }

        // reduce the two k-halves via smem
        {
            int rr = mt * 16 + gid;
            float* gh = ghs + kh * (64 * 24);
#pragma unroll
            for (int nt = 0; nt < 3; nt++) {
                gh[rr * 24 + nt * 8 + tig * 2 + 0] = acc[nt][0];
                gh[rr * 24 + nt * 8 + tig * 2 + 1] = acc[nt][1];
                gh[(rr + 8) * 24 + nt * 8 + tig * 2 + 0] = acc[nt][2];
                gh[(rr + 8) * 24 + nt * 8 + tig * 2 + 1] = acc[nt][3];
            }
        }
        __syncthreads();

        // gate math: rows r0 and r0+32, column j
        {
            float ghr = ghs[r0 * 24 + j] + ghs[64 * 24 + r0 * 24 + j] + bhr;
            float ghz = ghs[r0 * 24 + 8 + j] + ghs[64 * 24 + r0 * 24 + 8 + j] + bhz;
            float ghn = ghs[r0 * 24 + 16 + j] + ghs[64 * 24 + r0 * 24 + 16 + j] + bhn;
            float r = sigm(ir0 + bir + ghr);
            float z = sigm(iz0 + biz + ghz);
            float n = tanh_fast(in0 + bin + r * ghn);
            float hn = (1.0f - z) * n + z * hp0;
            hout[r0 * H + col] = hn;
            htfo[r0 * H + col] = f2tf(hn);

            int r1 = r0 + 32;
            ghr = ghs[r1 * 24 + j] + ghs[64 * 24 + r1 * 24 + j] + bhr;
            ghz = ghs[r1 * 24 + 8 + j] + ghs[64 * 24 + r1 * 24 + 8 + j] + bhz;
            ghn = ghs[r1 * 24 + 16 + j] + ghs[64 * 24 + r1 * 24 + 16 + j] + bhn;
            r = sigm(ir1 + bir + ghr);
            z = sigm(iz1 + biz + ghz);
            n = tanh_fast(in1 + bin + r * ghn);
            hn = (1.0f - z) * n + z * hp1;
            hout[r1 * H + col] = hn;
            htfo[r1 * H + col] = f2tf(hn);
        }

        // grid barrier: release/acquire only
        __syncthreads();
        if (tid == 0) {
            unsigned tgt = (unsigned)s + 1u;
            unsigned v = atom_add_release(&g_bar, 1u) + 1u;
            if (v == (unsigned)NCTA * tgt) {
                st_release(&g_gen, tgt);
            } else {
                while (ld_acquire(&g_gen) < tgt) {}
            }
        }
        __syncthreads();
    }
}

// ---------------- K3: decode + fc (parallel over k) ----------------
__global__ void __launch_bounds__(256) dec_kernel(
    const float* __restrict__ W_dec, const float* __restrict__ b_dec,
    const float* __restrict__ W_fc, const float* __restrict__ b_fc,
    float* __restrict__ out) {
    int b = blockIdx.x;
    int tid = threadIdx.x;
    __shared__ float hs[H];
    __shared__ float part[2][100];
    __shared__ float ds[100];
    const float* hrow = g_h[0] + b * H;   // SEQ even -> final h in buffer 0
    for (int i = tid; i < H; i += 256) hs[i] = hrow[i];
    __syncthreads();

    int o = tid & 127;
    int half = tid >> 7;
    if (o < 100) {
        float a0 = 0.0f, a1 = 0.0f, a2 = 0.0f, a3 = 0.0f;
        int kbase = half * 512;
        const float* wp = W_dec + (size_t)kbase * 100 + o;
#pragma unroll 4
        for (int kk = 0; kk < 512; kk += 4) {
            a0 += hs[kbase + kk + 0] * wp[(kk + 0) * 100];
            a1 += hs[kbase + kk + 1] * wp[(kk + 1) * 100];
            a2 += hs[kbase + kk + 2] * wp[(kk + 2) * 100];
            a3 += hs[kbase + kk + 3] * wp[(kk + 3) * 100];
        }
        part[half][o] = (a0 + a1) + (a2 + a3);
    }
    __syncthreads();
    if (tid < 100) {
        float d = part[0][tid] + part[1][tid] + b_dec[tid];
        ds[tid] = fmaxf(d, 0.0f);
    }
    __syncthreads();
    if (tid < 2) {
        float a = b_fc[tid];
        for (int jj = 0; jj < 100; jj++) a += ds[jj] * W_fc[jj * 2 + tid];
        out[b * 2 + tid] = a;
    }
}

// ---------------- launch ----------------
extern "C" void kernel_launch(void* const* d_in, const int* in_sizes, int n_in,
                              void* d_out, int out_size) {
    const int* ids = (const int*)d_in[0];
    const float* emb = (const float*)d_in[1];
    const float* W_ih = (const float*)d_in[2];
    const float* W_hh = (const float*)d_in[3];
    const float* b_ih = (const float*)d_in[4];
    const float* b_hh = (const float*)d_in[5];
    const float* W_dec = (const float*)d_in[6];
    const float* b_dec = (const float*)d_in[7];
    const float* W_fc = (const float*)d_in[8];
    const float* b_fc = (const float*)d_in[9];
    float* out = (float*)d_out;

    static bool attr_set = false;
    if (!attr_set) {
        cudaFuncSetAttribute(gru_persist_kernel,
                             cudaFuncAttributeMaxDynamicSharedMemorySize, SMEM_BYTES);
        cudaFuncSetAttribute(gi_kernel,
                             cudaFuncAttributeMaxDynamicSharedMemorySize, GI_SMEM_BYTES);
        attr_set = true;
    }

    init_kernel<<<256, 256>>>();

    dim3 g1(24, 256);
    gi_kernel<<<g1, 256, GI_SMEM_BYTES>>>(ids, emb, W_ih);

    gru_persist_kernel<<<NCTA, 256, SMEM_BYTES>>>(W_hh, b_ih, b_hh);

    dec_kernel<<<64, 256>>>(W_dec, b_dec, W_fc, b_fc, out);
}